// round 2
// baseline (speedup 1.0000x reference)
#include <cuda_runtime.h>
#include <math.h>

#define Tn 1024
#define Bn 8
#define Dn 512
#define Hn 8
#define DHn 64
#define NPAIR 64           // Hn*Bn
#define ROWS (Bn*Tn)       // 8192

// ---------------- scratch (device globals: allocation-free) ----------------
__device__ float g_xb[Bn*Tn*Dn];
__device__ float g_Q [Bn*Tn*Dn];
__device__ float g_K [Bn*Tn*Dn];
__device__ float g_V [Bn*Tn*Dn];
__device__ float g_tmp[Bn*Tn*Dn];
__device__ float g_S[(size_t)NPAIR*Tn*Tn];   // 256 MB score scratch
__device__ float g_invnorm[Bn*Dn];
__device__ float g_adj[Tn];

__device__ __forceinline__ float powtf(float v){
    return sqrtf(fmaxf(v,0.f)) - sqrtf(fmaxf(-v,0.f));
}

// ---------------- transposes ----------------
__global__ void k_transpose_in(const float* __restrict__ x){
    int idx = blockIdx.x*256 + threadIdx.x;          // [B,T,D] linear
    int d = idx & (Dn-1);
    int t = (idx >> 9) & (Tn-1);
    int b = idx >> 19;
    g_xb[idx] = x[(t*Bn + b)*Dn + d];
}

__global__ void k_transpose_out(float* __restrict__ out){
    int idx = blockIdx.x*256 + threadIdx.x;          // [T,B,D] linear
    int d = idx & (Dn-1);
    int b = (idx >> 9) & (Bn-1);
    int t = idx >> 12;
    out[idx] = g_xb[((b<<10) + t)*Dn + d];
}

// ---------------- adj table ----------------
__global__ void k_adj(const float* __restrict__ aw, const float* __restrict__ ab){
    int i = threadIdx.x;
    float dist = (float)i;
    g_adj[i] = expf(-fabsf(aw[0]*dist*dist - ab[0]));
}

// ---------------- QKV GEMM: C = xb @ W + b ----------------
__global__ __launch_bounds__(256) void k_gemm_qkv(
    const float* __restrict__ Wq, const float* __restrict__ Wk, const float* __restrict__ Wv,
    const float* __restrict__ bq, const float* __restrict__ bk, const float* __restrict__ bv,
    int layer)
{
    __shared__ __align__(16) float As[16][65];   // [k][m]
    __shared__ __align__(16) float Bs[16][68];   // [k][n]
    int tid = threadIdx.x;
    int z = blockIdx.z;
    const float* W    = (z==0 ? Wq : (z==1 ? Wk : Wv)) + layer*Dn*Dn;
    const float* bias = (z==0 ? bq : (z==1 ? bk : bv)) + layer*Dn;
    float* C          = (z==0 ? g_Q : (z==1 ? g_K : g_V));
    int m0 = blockIdx.y*64, n0 = blockIdx.x*64;
    int tx = tid & 15, ty = tid >> 4;
    int ar = tid >> 2, ac = (tid & 3) << 2;
    int br = tid >> 4, bc = (tid & 15) << 2;
    float acc[4][4] = {};
    for (int k0 = 0; k0 < Dn; k0 += 16){
        float4 a4 = *(const float4*)&g_xb[(m0+ar)*Dn + k0 + ac];
        As[ac+0][ar]=a4.x; As[ac+1][ar]=a4.y; As[ac+2][ar]=a4.z; As[ac+3][ar]=a4.w;
        *(float4*)&Bs[br][bc] = *(const float4*)&W[(size_t)(k0+br)*Dn + n0 + bc];
        __syncthreads();
#pragma unroll
        for (int kk=0; kk<16; kk++){
            float ra[4], rb[4];
#pragma unroll
            for (int i=0;i<4;i++) ra[i]=As[kk][ty*4+i];
#pragma unroll
            for (int j=0;j<4;j++) rb[j]=Bs[kk][tx*4+j];
#pragma unroll
            for (int i=0;i<4;i++)
#pragma unroll
                for (int j=0;j<4;j++) acc[i][j] = fmaf(ra[i], rb[j], acc[i][j]);
        }
        __syncthreads();
    }
    float4 b4 = *(const float4*)&bias[n0 + tx*4];
#pragma unroll
    for (int i=0;i<4;i++){
        float4 v;
        v.x=acc[i][0]+b4.x; v.y=acc[i][1]+b4.y; v.z=acc[i][2]+b4.z; v.w=acc[i][3]+b4.w;
        *(float4*)&C[(size_t)(m0+ty*4+i)*Dn + n0 + tx*4] = v;
    }
}

// ---------------- S = Q K^T * scale + adj, per (h,b) pair ----------------
__global__ __launch_bounds__(256) void k_attn_s(){
    __shared__ __align__(16) float Qs[64][68];   // [qrow][dh]
    __shared__ float Ks[64][65];                 // transposed: [dh][krow]
    int tid = threadIdx.x;
    int p = blockIdx.z;
    const float* Qp = g_Q + (size_t)p*Tn*DHn;
    const float* Kp = g_K + (size_t)p*Tn*DHn;
    int q0 = blockIdx.y*64, k0 = blockIdx.x*64;
#pragma unroll
    for (int i=0;i<4;i++){
        int idx = tid + i*256;
        int r = idx >> 4, c = (idx & 15) << 2;
        *(float4*)&Qs[r][c] = *(const float4*)&Qp[(q0+r)*DHn + c];
        float4 kv = *(const float4*)&Kp[(k0+r)*DHn + c];
        Ks[c+0][r]=kv.x; Ks[c+1][r]=kv.y; Ks[c+2][r]=kv.z; Ks[c+3][r]=kv.w;
    }
    __syncthreads();
    int tx = tid & 15, ty = tid >> 4;
    float acc[4][4]={};
#pragma unroll
    for (int kk=0; kk<64; kk++){
        float ra[4], rb[4];
#pragma unroll
        for (int i=0;i<4;i++) ra[i]=Qs[ty*4+i][kk];
#pragma unroll
        for (int j=0;j<4;j++) rb[j]=Ks[kk][tx*4+j];
#pragma unroll
        for (int i=0;i<4;i++)
#pragma unroll
            for (int j=0;j<4;j++) acc[i][j] = fmaf(ra[i], rb[j], acc[i][j]);
    }
    const float scale = 0.04419417382415922f;    // 1/sqrt(512)
#pragma unroll
    for (int i=0;i<4;i++){
        int q = q0 + ty*4 + i;
        float4 v;
        int kbase = k0 + tx*4;
        v.x = acc[i][0]*scale + g_adj[abs(q-(kbase+0))];
        v.y = acc[i][1]*scale + g_adj[abs(q-(kbase+1))];
        v.z = acc[i][2]*scale + g_adj[abs(q-(kbase+2))];
        v.w = acc[i][3]*scale + g_adj[abs(q-(kbase+3))];
        *(float4*)&g_S[((size_t)p*Tn + q)*Tn + kbase] = v;
    }
}

// ---------------- combined softmax: P = a*softmax_global + (1-a)*softmax_window ----------------
__global__ __launch_bounds__(128) void k_softmax(const float* __restrict__ alpha, int layer){
    __shared__ float shm[10];
    size_t row = blockIdx.x;
    int q = (int)(row & (Tn-1));
    float* Srow = g_S + row*Tn;
    int tid = threadIdx.x, lane = tid&31, wid = tid>>5;

    float s[8];
    float m = -1e30f;
#pragma unroll
    for (int j=0;j<8;j++){ s[j] = Srow[tid + j*128]; m = fmaxf(m, s[j]); }
#pragma unroll
    for (int o=16;o;o>>=1) m = fmaxf(m, __shfl_xor_sync(0xffffffffu,m,o));
    if (lane==0) shm[wid]=m;
    __syncthreads();
    if (tid==0) shm[4] = fmaxf(fmaxf(shm[0],shm[1]),fmaxf(shm[2],shm[3]));
    __syncthreads();
    float gmax = shm[4];

    float e[8]; float sum=0.f;
#pragma unroll
    for (int j=0;j<8;j++){ e[j] = expf(s[j]-gmax); sum += e[j]; }
#pragma unroll
    for (int o=16;o;o>>=1) sum += __shfl_xor_sync(0xffffffffu,sum,o);
    if (lane==0) shm[wid]=sum;
    __syncthreads();
    if (tid==0){
        shm[5] = shm[0]+shm[1]+shm[2]+shm[3];
        int lo = q-4; if (lo<0) lo=0;
        int hi = q+4; if (hi>Tn-1) hi=Tn-1;
        float lm=-1e30f;
        for (int k=lo;k<=hi;k++) lm = fmaxf(lm, Srow[k]);
        float ls=0.f;
        for (int k=lo;k<=hi;k++) ls += expf(Srow[k]-lm);
        shm[6]=lm; shm[7]=1.f/ls;
    }
    __syncthreads();
    float a    = 1.f/(1.f+expf(-alpha[layer]));
    float ginv = a/shm[5];
    float lm   = shm[6];
    float linv = (1.f-a)*shm[7];
    int lo = (q-4>0)? q-4 : 0;
    int hi = (q+4<Tn-1)? q+4 : Tn-1;
#pragma unroll
    for (int j=0;j<8;j++){
        int k = tid + j*128;
        float v = e[j]*ginv;
        if (k>=lo && k<=hi) v += expf(s[j]-lm)*linv;
        Srow[k] = v;
    }
}

// ---------------- O = P @ V, fused power transform ----------------
__global__ __launch_bounds__(256) void k_pv(){
    __shared__ __align__(16) float Ps[64][36];   // [qrow][k]
    __shared__ __align__(16) float Vs[32][68];   // [k][dh]
    int tid = threadIdx.x;
    int p  = blockIdx.y;
    int q0 = blockIdx.x*64;
    const float* Vp = g_V + (size_t)p*Tn*DHn;
    const float* Sp = g_S + (size_t)p*Tn*Tn;
    int tx = tid&15, ty = tid>>4;
    float acc[4][4]={};
    for (int k0=0;k0<Tn;k0+=32){
#pragma unroll
        for (int i=0;i<2;i++){
            int idx = tid + i*256;
            int r  = idx>>3, c  = (idx&7)<<2;
            *(float4*)&Ps[r][c]   = *(const float4*)&Sp[(size_t)(q0+r)*Tn + k0 + c];
            int vr = idx>>4, vc = (idx&15)<<2;
            *(float4*)&Vs[vr][vc] = *(const float4*)&Vp[(k0+vr)*DHn + vc];
        }
        __syncthreads();
#pragma unroll
        for (int kk=0;kk<32;kk++){
            float ra[4],rb[4];
#pragma unroll
            for (int i=0;i<4;i++) ra[i]=Ps[ty*4+i][kk];
#pragma unroll
            for (int j=0;j<4;j++) rb[j]=Vs[kk][tx*4+j];
#pragma unroll
            for (int i=0;i<4;i++)
#pragma unroll
                for (int j=0;j<4;j++) acc[i][j] = fmaf(ra[i], rb[j], acc[i][j]);
        }
        __syncthreads();
    }
#pragma unroll
    for (int i=0;i<4;i++){
        int q = q0 + ty*4 + i;
        float4 v;
        v.x = powtf(acc[i][0]); v.y = powtf(acc[i][1]);
        v.z = powtf(acc[i][2]); v.w = powtf(acc[i][3]);
        *(float4*)&g_tmp[(size_t)p*Tn*DHn + q*DHn + tx*4] = v;
    }
}

// ---------------- column L2 norms over seq axis (per b,d) ----------------
__global__ void k_colnorm(){
    int tid = threadIdx.x;
    int col = blockIdx.x*8 + (tid>>5);   // 0..4095
    int lane = tid&31;
    int b = col >> 9, d = col & (Dn-1);
    const float* base = g_tmp + (size_t)b*Tn*Dn + d;
    float sum = 0.f;
    for (int t=lane; t<Tn; t+=32){ float v = base[(size_t)t*Dn]; sum = fmaf(v,v,sum); }
#pragma unroll
    for (int o=16;o;o>>=1) sum += __shfl_xor_sync(0xffffffffu,sum,o);
    if (lane==0) g_invnorm[col] = 1.f/fmaxf(sqrtf(sum), 1e-12f);
}

// ---------------- out proj: xb = xb + (tmp/norm) @ Wo + bo ----------------
__global__ __launch_bounds__(256) void k_gemm_out(
    const float* __restrict__ Wo, const float* __restrict__ bo, int layer)
{
    __shared__ __align__(16) float As[16][65];
    __shared__ __align__(16) float Bs[16][68];
    int tid = threadIdx.x;
    const float* W    = Wo + (size_t)layer*Dn*Dn;
    const float* bias = bo + layer*Dn;
    int m0 = blockIdx.y*64, n0 = blockIdx.x*64;
    int tx = tid & 15, ty = tid >> 4;
    int ar = tid >> 2, ac = (tid & 3) << 2;
    int br = tid >> 4, bc = (tid & 15) << 2;
    float acc[4][4] = {};
    for (int k0 = 0; k0 < Dn; k0 += 16){
        int arow = m0+ar;
        float4 a4 = *(const float4*)&g_tmp[(size_t)arow*Dn + k0 + ac];
        float4 s4 = *(const float4*)&g_invnorm[(arow>>10)*Dn + k0 + ac];
        a4.x*=s4.x; a4.y*=s4.y; a4.z*=s4.z; a4.w*=s4.w;
        As[ac+0][ar]=a4.x; As[ac+1][ar]=a4.y; As[ac+2][ar]=a4.z; As[ac+3][ar]=a4.w;
        *(float4*)&Bs[br][bc] = *(const float4*)&W[(size_t)(k0+br)*Dn + n0 + bc];
        __syncthreads();
#pragma unroll
        for (int kk=0; kk<16; kk++){
            float ra[4], rb[4];
#pragma unroll
            for (int i=0;i<4;i++) ra[i]=As[kk][ty*4+i];
#pragma unroll
            for (int j=0;j<4;j++) rb[j]=Bs[kk][tx*4+j];
#pragma unroll
            for (int i=0;i<4;i++)
#pragma unroll
                for (int j=0;j<4;j++) acc[i][j] = fmaf(ra[i], rb[j], acc[i][j]);
        }
        __syncthreads();
    }
    float4 b4 = *(const float4*)&bias[n0 + tx*4];
#pragma unroll
    for (int i=0;i<4;i++){
        int m = m0+ty*4+i;
        float4 r4 = *(const float4*)&g_xb[(size_t)m*Dn + n0 + tx*4];
        float4 v;
        v.x=acc[i][0]+b4.x+r4.x; v.y=acc[i][1]+b4.y+r4.y;
        v.z=acc[i][2]+b4.z+r4.z; v.w=acc[i][3]+b4.w+r4.w;
        *(float4*)&g_xb[(size_t)m*Dn + n0 + tx*4] = v;
    }
}

// ---------------- LayerNorm over D, in place on g_xb ----------------
__global__ __launch_bounds__(128) void k_ln(
    const float* __restrict__ lng, const float* __restrict__ lnb, int layer)
{
    __shared__ float shm[10];
    int r = blockIdx.x;
    int tid = threadIdx.x, lane = tid&31, wid = tid>>5;
    float v[4];
    float sum=0.f, sq=0.f;
#pragma unroll
    for (int j=0;j<4;j++){
        v[j] = g_xb[(size_t)r*Dn + tid + j*128];
        sum += v[j]; sq = fmaf(v[j],v[j],sq);
    }
#pragma unroll
    for (int o=16;o;o>>=1){ sum += __shfl_xor_sync(0xffffffffu,sum,o); sq += __shfl_xor_sync(0xffffffffu,sq,o); }
    if (lane==0){ shm[wid]=sum; shm[4+wid]=sq; }
    __syncthreads();
    if (tid==0){ shm[8]=shm[0]+shm[1]+shm[2]+shm[3]; shm[9]=shm[4]+shm[5]+shm[6]+shm[7]; }
    __syncthreads();
    float mu  = shm[8]*(1.f/Dn);
    float var = shm[9]*(1.f/Dn) - mu*mu;
    float rstd = rsqrtf(fmaxf(var,0.f) + 1e-5f);
    const float* g  = lng + layer*Dn;
    const float* bb = lnb + layer*Dn;
#pragma unroll
    for (int j=0;j<4;j++){
        int d = tid + j*128;
        g_xb[(size_t)r*Dn + d] = (v[j]-mu)*rstd*g[d] + bb[d];
    }
}

// ---------------- launch ----------------
extern "C" void kernel_launch(void* const* d_in, const int* in_sizes, int n_in,
                              void* d_out, int out_size)
{
    const float* x     = (const float*)d_in[0];
    const float* Wq    = (const float*)d_in[1];
    const float* bq    = (const float*)d_in[2];
    const float* Wk    = (const float*)d_in[3];
    const float* bk    = (const float*)d_in[4];
    const float* Wv    = (const float*)d_in[5];
    const float* bv    = (const float*)d_in[6];
    const float* Wo    = (const float*)d_in[7];
    const float* bo    = (const float*)d_in[8];
    const float* alpha = (const float*)d_in[9];
    const float* ln_g  = (const float*)d_in[10];
    const float* ln_b  = (const float*)d_in[11];
    const float* adj_w = (const float*)d_in[12];
    const float* adj_b = (const float*)d_in[13];
    float* out = (float*)d_out;

    k_transpose_in<<<(ROWS*Dn)/256, 256>>>(x);
    k_adj<<<1, Tn>>>(adj_w, adj_b);
    for (int l=0; l<2; l++){
        k_gemm_qkv<<<dim3(8,128,3), 256>>>(Wq,Wk,Wv,bq,bk,bv,l);
        k_attn_s<<<dim3(16,16,64), 256>>>();
        k_softmax<<<NPAIR*Tn, 128>>>(alpha, l);
        k_pv<<<dim3(16,64), 256>>>();
        k_colnorm<<<512, 256>>>();
        k_gemm_out<<<dim3(8,128), 256>>>(Wo, bo, l);
        k_ln<<<ROWS, 128>>>(ln_g, ln_b, l);
    }
    k_transpose_out<<<(ROWS*Dn)/256, 256>>>(out);
}

// round 3
// speedup vs baseline: 2.2898x; 2.2898x over previous
#include <cuda_runtime.h>
#include <math.h>
#include <stdint.h>

#define Tn 1024
#define Bn 8
#define Dn 512
#define Hn 8
#define DHn 64
#define NPAIR 64           // Hn*Bn
#define ROWS (Bn*Tn)       // 8192

// ---------------- scratch (device globals: allocation-free) ----------------
__device__ float g_xb[Bn*Tn*Dn];
__device__ float g_Q [Bn*Tn*Dn];
__device__ float g_K [Bn*Tn*Dn];
__device__ float g_V [Bn*Tn*Dn];
__device__ float g_tmp[Bn*Tn*Dn];
__device__ float g_S[(size_t)NPAIR*Tn*Tn];   // 256 MB score scratch
__device__ float g_invnorm[Bn*Dn];
__device__ float g_adj[Tn];

__device__ __forceinline__ float powtf(float v){
    return sqrtf(fmaxf(v,0.f)) - sqrtf(fmaxf(-v,0.f));
}

__device__ __forceinline__ uint32_t f2tf(float f){
    uint32_t u; asm("cvt.rna.tf32.f32 %0, %1;" : "=r"(u) : "f"(f)); return u;
}

// mma.sync m16n8k8 tf32, fp32 accum, row.col
__device__ __forceinline__ void mma8(float* c, const uint32_t* a, const uint32_t* b){
    asm volatile(
        "mma.sync.aligned.m16n8k8.row.col.f32.tf32.tf32.f32 "
        "{%0,%1,%2,%3},{%4,%5,%6,%7},{%8,%9},{%0,%1,%2,%3};"
        : "+f"(c[0]),"+f"(c[1]),"+f"(c[2]),"+f"(c[3])
        : "r"(a[0]),"r"(a[1]),"r"(a[2]),"r"(a[3]),"r"(b[0]),"r"(b[1]));
}

// ---------------- transposes ----------------
__global__ void k_transpose_in(const float* __restrict__ x){
    int idx = blockIdx.x*256 + threadIdx.x;          // [B,T,D] linear
    int d = idx & (Dn-1);
    int t = (idx >> 9) & (Tn-1);
    int b = idx >> 19;
    g_xb[idx] = x[(t*Bn + b)*Dn + d];
}

__global__ void k_transpose_out(float* __restrict__ out){
    int idx = blockIdx.x*256 + threadIdx.x;          // [T,B,D] linear
    int d = idx & (Dn-1);
    int b = (idx >> 9) & (Bn-1);
    int t = idx >> 12;
    out[idx] = g_xb[((b<<10) + t)*Dn + d];
}

// ---------------- adj table ----------------
__global__ void k_adj(const float* __restrict__ aw, const float* __restrict__ ab){
    int i = threadIdx.x;
    float dist = (float)i;
    g_adj[i] = expf(-fabsf(aw[0]*dist*dist - ab[0]));
}

// ================= tf32 projection GEMM: C = A @ W + b =================
// M=8192, N=512, K=512. Block 128x64, BK=32. 8 warps as 4(m) x 2(n), warp 32x32.
__global__ __launch_bounds__(256) void k_proj_qkv(
    const float* __restrict__ Wq, const float* __restrict__ Wk, const float* __restrict__ Wv,
    const float* __restrict__ bq, const float* __restrict__ bk, const float* __restrict__ bv,
    int layer)
{
    __shared__ uint32_t As[128][36];   // [m][k], stride%32==4 -> a-frag conflict free
    __shared__ uint32_t Bs[32][72];    // [k][n], stride%32==8 -> b-frag conflict free
    int tid = threadIdx.x;
    int z = blockIdx.z;
    const float* W    = (z==0 ? Wq : (z==1 ? Wk : Wv)) + (size_t)layer*Dn*Dn;
    const float* bias = (z==0 ? bq : (z==1 ? bk : bv)) + layer*Dn;
    float* C          = (z==0 ? g_Q : (z==1 ? g_K : g_V));
    int m0 = blockIdx.y*128, n0 = blockIdx.x*64;
    int wid = tid>>5, lane = tid&31, g = lane>>2, t = lane&3;
    int m_off = (wid>>1)*32, n_off = (wid&1)*32;

    float c[2][4][4] = {};
    int arow = tid>>3, acol = (tid&7)*4;
    int brow = tid>>4, bcol = (tid&15)*4;

    for (int k0=0; k0<Dn; k0+=32){
#pragma unroll
        for (int i=0;i<4;i++){
            float4 v = *(const float4*)&g_xb[(size_t)(m0+arow+i*32)*Dn + k0 + acol];
            As[arow+i*32][acol+0]=f2tf(v.x); As[arow+i*32][acol+1]=f2tf(v.y);
            As[arow+i*32][acol+2]=f2tf(v.z); As[arow+i*32][acol+3]=f2tf(v.w);
        }
#pragma unroll
        for (int i=0;i<2;i++){
            float4 v = *(const float4*)&W[(size_t)(k0+brow+i*16)*Dn + n0 + bcol];
            Bs[brow+i*16][bcol+0]=f2tf(v.x); Bs[brow+i*16][bcol+1]=f2tf(v.y);
            Bs[brow+i*16][bcol+2]=f2tf(v.z); Bs[brow+i*16][bcol+3]=f2tf(v.w);
        }
        __syncthreads();
#pragma unroll
        for (int ks=0; ks<4; ks++){
            uint32_t a[2][4], b[4][2];
#pragma unroll
            for (int mi=0;mi<2;mi++){
                int r = m_off+mi*16;
                a[mi][0]=As[r+g  ][ks*8+t];   a[mi][1]=As[r+g+8][ks*8+t];
                a[mi][2]=As[r+g  ][ks*8+t+4]; a[mi][3]=As[r+g+8][ks*8+t+4];
            }
#pragma unroll
            for (int ni=0;ni<4;ni++){
                b[ni][0]=Bs[ks*8+t  ][n_off+ni*8+g];
                b[ni][1]=Bs[ks*8+t+4][n_off+ni*8+g];
            }
#pragma unroll
            for (int mi=0;mi<2;mi++)
#pragma unroll
                for (int ni=0;ni<4;ni++) mma8(c[mi][ni], a[mi], b[ni]);
        }
        __syncthreads();
    }
#pragma unroll
    for (int mi=0;mi<2;mi++){
#pragma unroll
        for (int ni=0;ni<4;ni++){
            int row = m0 + m_off + mi*16 + g;
            int col = n0 + n_off + ni*8 + 2*t;
            float b0 = bias[col], b1 = bias[col+1];
            float2 v0 = {c[mi][ni][0]+b0, c[mi][ni][1]+b1};
            float2 v1 = {c[mi][ni][2]+b0, c[mi][ni][3]+b1};
            *(float2*)&C[(size_t)row*Dn + col]     = v0;
            *(float2*)&C[(size_t)(row+8)*Dn + col] = v1;
        }
    }
}

// ---- out proj: g_xb = g_xb + (g_tmp * invnorm) @ Wo + bo ----
__global__ __launch_bounds__(256) void k_proj_out(
    const float* __restrict__ Wo, const float* __restrict__ bo, int layer)
{
    __shared__ uint32_t As[128][36];
    __shared__ uint32_t Bs[32][72];
    int tid = threadIdx.x;
    const float* W    = Wo + (size_t)layer*Dn*Dn;
    const float* bias = bo + layer*Dn;
    int m0 = blockIdx.y*128, n0 = blockIdx.x*64;
    int wid = tid>>5, lane = tid&31, g = lane>>2, t = lane&3;
    int m_off = (wid>>1)*32, n_off = (wid&1)*32;

    float c[2][4][4] = {};
    int arow = tid>>3, acol = (tid&7)*4;
    int brow = tid>>4, bcol = (tid&15)*4;

    for (int k0=0; k0<Dn; k0+=32){
#pragma unroll
        for (int i=0;i<4;i++){
            int m = m0+arow+i*32;
            float4 v = *(const float4*)&g_tmp[(size_t)m*Dn + k0 + acol];
            float4 s = *(const float4*)&g_invnorm[(m>>10)*Dn + k0 + acol];
            As[arow+i*32][acol+0]=f2tf(v.x*s.x); As[arow+i*32][acol+1]=f2tf(v.y*s.y);
            As[arow+i*32][acol+2]=f2tf(v.z*s.z); As[arow+i*32][acol+3]=f2tf(v.w*s.w);
        }
#pragma unroll
        for (int i=0;i<2;i++){
            float4 v = *(const float4*)&W[(size_t)(k0+brow+i*16)*Dn + n0 + bcol];
            Bs[brow+i*16][bcol+0]=f2tf(v.x); Bs[brow+i*16][bcol+1]=f2tf(v.y);
            Bs[brow+i*16][bcol+2]=f2tf(v.z); Bs[brow+i*16][bcol+3]=f2tf(v.w);
        }
        __syncthreads();
#pragma unroll
        for (int ks=0; ks<4; ks++){
            uint32_t a[2][4], b[4][2];
#pragma unroll
            for (int mi=0;mi<2;mi++){
                int r = m_off+mi*16;
                a[mi][0]=As[r+g  ][ks*8+t];   a[mi][1]=As[r+g+8][ks*8+t];
                a[mi][2]=As[r+g  ][ks*8+t+4]; a[mi][3]=As[r+g+8][ks*8+t+4];
            }
#pragma unroll
            for (int ni=0;ni<4;ni++){
                b[ni][0]=Bs[ks*8+t  ][n_off+ni*8+g];
                b[ni][1]=Bs[ks*8+t+4][n_off+ni*8+g];
            }
#pragma unroll
            for (int mi=0;mi<2;mi++)
#pragma unroll
                for (int ni=0;ni<4;ni++) mma8(c[mi][ni], a[mi], b[ni]);
        }
        __syncthreads();
    }
#pragma unroll
    for (int mi=0;mi<2;mi++){
#pragma unroll
        for (int ni=0;ni<4;ni++){
            int row = m0 + m_off + mi*16 + g;
            int col = n0 + n_off + ni*8 + 2*t;
            float b0 = bias[col], b1 = bias[col+1];
            float2 r0 = *(float2*)&g_xb[(size_t)row*Dn + col];
            float2 r1 = *(float2*)&g_xb[(size_t)(row+8)*Dn + col];
            float2 v0 = {c[mi][ni][0]+b0+r0.x, c[mi][ni][1]+b1+r0.y};
            float2 v1 = {c[mi][ni][2]+b0+r1.x, c[mi][ni][3]+b1+r1.y};
            *(float2*)&g_xb[(size_t)row*Dn + col]     = v0;
            *(float2*)&g_xb[(size_t)(row+8)*Dn + col] = v1;
        }
    }
}

// ================= S = Q K^T * scale + adj (tf32 mma) =================
// per pair: M=N=1024, K=64. Block 128x128. 8 warps 2(m)x4(n), warp 64x32.
__global__ __launch_bounds__(256) void k_attn_s(){
    extern __shared__ uint32_t sh[];
    uint32_t (*Qs)[68] = (uint32_t(*)[68])sh;            // [128][68]
    uint32_t (*Ks)[68] = (uint32_t(*)[68])(sh + 128*68); // [128][68]
    int tid = threadIdx.x;
    int p = blockIdx.z;
    const float* Qp = g_Q + (size_t)p*Tn*DHn;
    const float* Kp = g_K + (size_t)p*Tn*DHn;
    int q0 = blockIdx.y*128, k0 = blockIdx.x*128;
    int wid = tid>>5, lane = tid&31, g = lane>>2, t = lane&3;
    int m_off = (wid>>2)*64, n_off = (wid&3)*32;

    int lrow = tid>>4, lcol = (tid&15)*4;
#pragma unroll
    for (int i=0;i<8;i++){
        int r = lrow + i*16;
        float4 q4 = *(const float4*)&Qp[(size_t)(q0+r)*DHn + lcol];
        Qs[r][lcol+0]=f2tf(q4.x); Qs[r][lcol+1]=f2tf(q4.y);
        Qs[r][lcol+2]=f2tf(q4.z); Qs[r][lcol+3]=f2tf(q4.w);
        float4 k4 = *(const float4*)&Kp[(size_t)(k0+r)*DHn + lcol];
        Ks[r][lcol+0]=f2tf(k4.x); Ks[r][lcol+1]=f2tf(k4.y);
        Ks[r][lcol+2]=f2tf(k4.z); Ks[r][lcol+3]=f2tf(k4.w);
    }
    __syncthreads();

    float c[4][4][4] = {};
#pragma unroll
    for (int ks=0; ks<8; ks++){
        uint32_t a[4][4], b[4][2];
#pragma unroll
        for (int mi=0;mi<4;mi++){
            int r = m_off+mi*16;
            a[mi][0]=Qs[r+g  ][ks*8+t];   a[mi][1]=Qs[r+g+8][ks*8+t];
            a[mi][2]=Qs[r+g  ][ks*8+t+4]; a[mi][3]=Qs[r+g+8][ks*8+t+4];
        }
#pragma unroll
        for (int ni=0;ni<4;ni++){
            b[ni][0]=Ks[n_off+ni*8+g][ks*8+t];
            b[ni][1]=Ks[n_off+ni*8+g][ks*8+t+4];
        }
#pragma unroll
        for (int mi=0;mi<4;mi++)
#pragma unroll
            for (int ni=0;ni<4;ni++) mma8(c[mi][ni], a[mi], b[ni]);
    }

    const float scale = 0.04419417382415922f;    // 1/sqrt(512)
    float* Sp = g_S + (size_t)p*Tn*Tn;
#pragma unroll
    for (int mi=0;mi<4;mi++){
#pragma unroll
        for (int ni=0;ni<4;ni++){
            int q  = q0 + m_off + mi*16 + g;
            int kk = k0 + n_off + ni*8 + 2*t;
            float2 v0 = {c[mi][ni][0]*scale + g_adj[abs(q-kk)],
                         c[mi][ni][1]*scale + g_adj[abs(q-kk-1)]};
            float2 v1 = {c[mi][ni][2]*scale + g_adj[abs(q+8-kk)],
                         c[mi][ni][3]*scale + g_adj[abs(q+8-kk-1)]};
            *(float2*)&Sp[(size_t)q*Tn + kk]     = v0;
            *(float2*)&Sp[(size_t)(q+8)*Tn + kk] = v1;
        }
    }
}

// ---------------- combined softmax: P = a*softmax_global + (1-a)*softmax_window ----------------
__global__ __launch_bounds__(128) void k_softmax(const float* __restrict__ alpha, int layer){
    __shared__ float shm[10];
    size_t row = blockIdx.x;
    int q = (int)(row & (Tn-1));
    float* Srow = g_S + row*Tn;
    int tid = threadIdx.x, lane = tid&31, wid = tid>>5;

    float s[8];
    float m = -1e30f;
#pragma unroll
    for (int j=0;j<8;j++){ s[j] = Srow[tid + j*128]; m = fmaxf(m, s[j]); }
#pragma unroll
    for (int o=16;o;o>>=1) m = fmaxf(m, __shfl_xor_sync(0xffffffffu,m,o));
    if (lane==0) shm[wid]=m;
    __syncthreads();
    if (tid==0) shm[4] = fmaxf(fmaxf(shm[0],shm[1]),fmaxf(shm[2],shm[3]));
    __syncthreads();
    float gmax = shm[4];

    float e[8]; float sum=0.f;
#pragma unroll
    for (int j=0;j<8;j++){ e[j] = expf(s[j]-gmax); sum += e[j]; }
#pragma unroll
    for (int o=16;o;o>>=1) sum += __shfl_xor_sync(0xffffffffu,sum,o);
    if (lane==0) shm[wid]=sum;
    __syncthreads();
    if (tid==0){
        shm[5] = shm[0]+shm[1]+shm[2]+shm[3];
        int lo = q-4; if (lo<0) lo=0;
        int hi = q+4; if (hi>Tn-1) hi=Tn-1;
        float lm=-1e30f;
        for (int k=lo;k<=hi;k++) lm = fmaxf(lm, Srow[k]);
        float ls=0.f;
        for (int k=lo;k<=hi;k++) ls += expf(Srow[k]-lm);
        shm[6]=lm; shm[7]=1.f/ls;
    }
    __syncthreads();
    float a    = 1.f/(1.f+expf(-alpha[layer]));
    float ginv = a/shm[5];
    float lm   = shm[6];
    float linv = (1.f-a)*shm[7];
    int lo = (q-4>0)? q-4 : 0;
    int hi = (q+4<Tn-1)? q+4 : Tn-1;
#pragma unroll
    for (int j=0;j<8;j++){
        int k = tid + j*128;
        float v = e[j]*ginv;
        if (k>=lo && k<=hi) v += expf(s[j]-lm)*linv;
        Srow[k] = v;
    }
}

// ================= O = P @ V (tf32 mma), fused power transform =================
// per pair: M=1024, N=64, K=1024. Block 128x64, BK=64. 8 warps 4(m)x2(n), warp 32x32.
__global__ __launch_bounds__(256) void k_pv(){
    extern __shared__ uint32_t sh[];
    uint32_t (*Ps)[68] = (uint32_t(*)[68])sh;            // [128][68]
    uint32_t (*Vs)[72] = (uint32_t(*)[72])(sh + 128*68); // [64][72]
    int tid = threadIdx.x;
    int p  = blockIdx.y;
    int q0 = blockIdx.x*128;
    const float* Vp = g_V + (size_t)p*Tn*DHn;
    const float* Sp = g_S + (size_t)p*Tn*Tn;
    int wid = tid>>5, lane = tid&31, g = lane>>2, t = lane&3;
    int m_off = (wid>>1)*32, n_off = (wid&1)*32;

    int lrow = tid>>4, lcol = (tid&15)*4;
    float c[2][4][4] = {};
    for (int k0=0; k0<Tn; k0+=64){
#pragma unroll
        for (int i=0;i<8;i++){
            int r = lrow + i*16;
            float4 v = *(const float4*)&Sp[(size_t)(q0+r)*Tn + k0 + lcol];
            Ps[r][lcol+0]=f2tf(v.x); Ps[r][lcol+1]=f2tf(v.y);
            Ps[r][lcol+2]=f2tf(v.z); Ps[r][lcol+3]=f2tf(v.w);
        }
#pragma unroll
        for (int i=0;i<4;i++){
            int r = lrow + i*16;
            float4 v = *(const float4*)&Vp[(size_t)(k0+r)*DHn + lcol];
            Vs[r][lcol+0]=f2tf(v.x); Vs[r][lcol+1]=f2tf(v.y);
            Vs[r][lcol+2]=f2tf(v.z); Vs[r][lcol+3]=f2tf(v.w);
        }
        __syncthreads();
#pragma unroll
        for (int ks=0; ks<8; ks++){
            uint32_t a[2][4], b[4][2];
#pragma unroll
            for (int mi=0;mi<2;mi++){
                int r = m_off+mi*16;
                a[mi][0]=Ps[r+g  ][ks*8+t];   a[mi][1]=Ps[r+g+8][ks*8+t];
                a[mi][2]=Ps[r+g  ][ks*8+t+4]; a[mi][3]=Ps[r+g+8][ks*8+t+4];
            }
#pragma unroll
            for (int ni=0;ni<4;ni++){
                b[ni][0]=Vs[ks*8+t  ][n_off+ni*8+g];
                b[ni][1]=Vs[ks*8+t+4][n_off+ni*8+g];
            }
#pragma unroll
            for (int mi=0;mi<2;mi++)
#pragma unroll
                for (int ni=0;ni<4;ni++) mma8(c[mi][ni], a[mi], b[ni]);
        }
        __syncthreads();
    }
#pragma unroll
    for (int mi=0;mi<2;mi++){
#pragma unroll
        for (int ni=0;ni<4;ni++){
            int q   = q0 + m_off + mi*16 + g;
            int col = n_off + ni*8 + 2*t;
            float2 v0 = {powtf(c[mi][ni][0]), powtf(c[mi][ni][1])};
            float2 v1 = {powtf(c[mi][ni][2]), powtf(c[mi][ni][3])};
            *(float2*)&g_tmp[(size_t)p*Tn*DHn + (size_t)q*DHn + col]     = v0;
            *(float2*)&g_tmp[(size_t)p*Tn*DHn + (size_t)(q+8)*DHn + col] = v1;
        }
    }
}

// ---------------- column L2 norms over seq axis (per b,d) ----------------
__global__ void k_colnorm(){
    int tid = threadIdx.x;
    int col = blockIdx.x*8 + (tid>>5);   // 0..4095
    int lane = tid&31;
    int b = col >> 9, d = col & (Dn-1);
    const float* base = g_tmp + (size_t)b*Tn*Dn + d;
    float sum = 0.f;
    for (int t=lane; t<Tn; t+=32){ float v = base[(size_t)t*Dn]; sum = fmaf(v,v,sum); }
#pragma unroll
    for (int o=16;o;o>>=1) sum += __shfl_xor_sync(0xffffffffu,sum,o);
    if (lane==0) g_invnorm[col] = 1.f/fmaxf(sqrtf(sum), 1e-12f);
}

// ---------------- LayerNorm over D, in place on g_xb ----------------
__global__ __launch_bounds__(128) void k_ln(
    const float* __restrict__ lng, const float* __restrict__ lnb, int layer)
{
    __shared__ float shm[10];
    int r = blockIdx.x;
    int tid = threadIdx.x, lane = tid&31, wid = tid>>5;
    float v[4];
    float sum=0.f, sq=0.f;
#pragma unroll
    for (int j=0;j<4;j++){
        v[j] = g_xb[(size_t)r*Dn + tid + j*128];
        sum += v[j]; sq = fmaf(v[j],v[j],sq);
    }
#pragma unroll
    for (int o=16;o;o>>=1){ sum += __shfl_xor_sync(0xffffffffu,sum,o); sq += __shfl_xor_sync(0xffffffffu,sq,o); }
    if (lane==0){ shm[wid]=sum; shm[4+wid]=sq; }
    __syncthreads();
    if (tid==0){ shm[8]=shm[0]+shm[1]+shm[2]+shm[3]; shm[9]=shm[4]+shm[5]+shm[6]+shm[7]; }
    __syncthreads();
    float mu  = shm[8]*(1.f/Dn);
    float var = shm[9]*(1.f/Dn) - mu*mu;
    float rstd = rsqrtf(fmaxf(var,0.f) + 1e-5f);
    const float* gg = lng + layer*Dn;
    const float* bb = lnb + layer*Dn;
#pragma unroll
    for (int j=0;j<4;j++){
        int d = tid + j*128;
        g_xb[(size_t)r*Dn + d] = (v[j]-mu)*rstd*gg[d] + bb[d];
    }
}

// ---------------- launch ----------------
extern "C" void kernel_launch(void* const* d_in, const int* in_sizes, int n_in,
                              void* d_out, int out_size)
{
    const float* x     = (const float*)d_in[0];
    const float* Wq    = (const float*)d_in[1];
    const float* bq    = (const float*)d_in[2];
    const float* Wk    = (const float*)d_in[3];
    const float* bk    = (const float*)d_in[4];
    const float* Wv    = (const float*)d_in[5];
    const float* bv    = (const float*)d_in[6];
    const float* Wo    = (const float*)d_in[7];
    const float* bo    = (const float*)d_in[8];
    const float* alpha = (const float*)d_in[9];
    const float* ln_g  = (const float*)d_in[10];
    const float* ln_b  = (const float*)d_in[11];
    const float* adj_w = (const float*)d_in[12];
    const float* adj_b = (const float*)d_in[13];
    float* out = (float*)d_out;

    const int attn_smem = 2*128*68*4;                 // 69632 B
    const int pv_smem   = (128*68 + 64*72)*4;         // 53248 B
    cudaFuncSetAttribute(k_attn_s, cudaFuncAttributeMaxDynamicSharedMemorySize, attn_smem);
    cudaFuncSetAttribute(k_pv,     cudaFuncAttributeMaxDynamicSharedMemorySize, pv_smem);

    k_transpose_in<<<(ROWS*Dn)/256, 256>>>(x);
    k_adj<<<1, Tn>>>(adj_w, adj_b);
    for (int l=0; l<2; l++){
        k_proj_qkv<<<dim3(8,64,3), 256>>>(Wq,Wk,Wv,bq,bk,bv,l);
        k_attn_s<<<dim3(8,8,64), 256, attn_smem>>>();
        k_softmax<<<NPAIR*Tn, 128>>>(alpha, l);
        k_pv<<<dim3(8,64), 256, pv_smem>>>();
        k_colnorm<<<512, 256>>>();
        k_proj_out<<<dim3(8,64), 256>>>(Wo, bo, l);
        k_ln<<<ROWS, 128>>>(ln_g, ln_b, l);
    }
    k_transpose_out<<<(ROWS*Dn)/256, 256>>>(out);
}